// round 2
// baseline (speedup 1.0000x reference)
#include <cuda_runtime.h>
#include <math.h>

#define BB   2
#define SS   2048
#define HH   16
#define DK   64
#define DM   1024
#define MTOT (BB*SS)          // 4096
#define BHT  (BB*HH)          // 32

// Scratch (allocation-free rule: __device__ globals)
__device__ float g_q[BB*HH*SS*DK];     // [b,h,s,d]
__device__ float g_k[BB*HH*SS*DK];
__device__ float g_v[BB*HH*SS*DK];
__device__ float g_ctx[BB*SS*DM];      // [b,s,dm]

// ---------------------------------------------------------------------------
// SGEMM: C[m][n] = sum_k A[m][k] * W[n][k]   (A: MxK row-major, W: NxK row-major)
// MODE 0: z in {0,1,2} selects Wq/Wk/Wv, epilogue scatters into [b,h,s,d]
// MODE 1: plain row-major output to C0
// ---------------------------------------------------------------------------
template<int MODE>
__global__ void __launch_bounds__(256, 2)
sgemm_kernel(const float* __restrict__ A,
             const float* __restrict__ W0, const float* __restrict__ W1,
             const float* __restrict__ W2,
             float* __restrict__ C0, float* __restrict__ C1, float* __restrict__ C2)
{
    __shared__ float As[16][128];
    __shared__ float Bs[16][128];

    const float* W;
    float* C;
    if (MODE == 0) {
        int z = blockIdx.z;
        W = (z == 0) ? W0 : ((z == 1) ? W1 : W2);
        C = (z == 0) ? C0 : ((z == 1) ? C1 : C2);
    } else {
        W = W0; C = C0;
    }

    const int tid = threadIdx.x;
    const int tr = tid >> 4;        // 0..15
    const int tc = tid & 15;        // 0..15
    const int m0 = blockIdx.y * 128;
    const int n0 = blockIdx.x * 128;

    float acc[8][8];
#pragma unroll
    for (int i = 0; i < 8; i++)
#pragma unroll
        for (int j = 0; j < 8; j++) acc[i][j] = 0.f;

    for (int k0 = 0; k0 < DM; k0 += 16) {
#pragma unroll
        for (int u = 0; u < 2; u++) {
            int qd  = tid + u * 256;         // 0..511
            int row = qd >> 2;               // 0..127
            int kc  = (qd & 3) << 2;         // 0,4,8,12
            float4 a4 = *(const float4*)(A + (size_t)(m0 + row) * DM + k0 + kc);
            As[kc + 0][row] = a4.x; As[kc + 1][row] = a4.y;
            As[kc + 2][row] = a4.z; As[kc + 3][row] = a4.w;
            float4 b4 = *(const float4*)(W + (size_t)(n0 + row) * DM + k0 + kc);
            Bs[kc + 0][row] = b4.x; Bs[kc + 1][row] = b4.y;
            Bs[kc + 2][row] = b4.z; Bs[kc + 3][row] = b4.w;
        }
        __syncthreads();
#pragma unroll
        for (int kk = 0; kk < 16; kk++) {
            float a[8], b[8];
            *(float4*)&a[0] = *(const float4*)&As[kk][tr * 8];
            *(float4*)&a[4] = *(const float4*)&As[kk][tr * 8 + 4];
            *(float4*)&b[0] = *(const float4*)&Bs[kk][tc * 8];
            *(float4*)&b[4] = *(const float4*)&Bs[kk][tc * 8 + 4];
#pragma unroll
            for (int i = 0; i < 8; i++)
#pragma unroll
                for (int j = 0; j < 8; j++)
                    acc[i][j] = fmaf(a[i], b[j], acc[i][j]);
        }
        __syncthreads();
    }

    if (MODE == 0) {
#pragma unroll
        for (int i = 0; i < 8; i++) {
            int m  = m0 + tr * 8 + i;
            int b_ = m >> 11;           // /2048
            int s  = m & 2047;
            int nbase = n0 + tc * 8;
            int h  = nbase >> 6;        // 8-wide chunk stays inside one head
            int d  = nbase & 63;
            float* dst = C + ((size_t)((b_ * HH + h) * SS + s)) * DK + d;
#pragma unroll
            for (int j = 0; j < 8; j++) dst[j] = acc[i][j];
        }
    } else {
#pragma unroll
        for (int i = 0; i < 8; i++) {
            int m = m0 + tr * 8 + i;
            float4* dst = (float4*)(C + (size_t)m * DM + n0 + tc * 8);
            dst[0] = make_float4(acc[i][0], acc[i][1], acc[i][2], acc[i][3]);
            dst[1] = make_float4(acc[i][4], acc[i][5], acc[i][6], acc[i][7]);
        }
    }
}

// ---------------------------------------------------------------------------
// RoPE in-place on q and k, layout [b,h,s,d]; pairs (2j, 2j+1), j=0..31
// ---------------------------------------------------------------------------
__global__ void rope_kernel(float* __restrict__ q, float* __restrict__ k)
{
    const int NP = BB * HH * SS * 32;   // pairs per array
    int idx = blockIdx.x * blockDim.x + threadIdx.x;
    if (idx >= 2 * NP) return;
    float* arr = (idx < NP) ? q : k;
    int p = (idx < NP) ? idx : idx - NP;

    int j = p & 31;
    int s = (p >> 5) & 2047;
    size_t base = ((size_t)(p >> 5)) * 64 + 2 * j;

    // inv_freq = 10000^(-j/32) = 2^(-j * log2(10000)/32)
    float inv_freq = exp2f(-(float)j * (13.287712379549449f / 32.0f));
    float ang = (float)s * inv_freq;
    float sn, cs;
    sincosf(ang, &sn, &cs);     // accurate range reduction (ang up to ~2047)

    float2* pp = (float2*)(arr + base);
    float2 xv = *pp;
    *pp = make_float2(xv.x * cs - xv.y * sn, xv.x * sn + xv.y * cs);
}

// ---------------------------------------------------------------------------
// Flash attention (causal), fp32. Br=Bc=64, d=64. 128 threads (ty 0..15, tx 0..7)
// Each thread: 4 query rows x 8 cols. Smem tiles stored transposed [d][r],
// row stride 65 (conflict-free transpose fill; uniform-d reads unaffected).
// ---------------------------------------------------------------------------
#define TP 65   // padded stride

__global__ void __launch_bounds__(128)
flash_kernel(const float* __restrict__ Q, const float* __restrict__ K,
             const float* __restrict__ V, float* __restrict__ ctx)
{
    extern __shared__ float sm[];
    float* Qt = sm;                 // [64][TP]  (d-major: Qt[d*TP + r])
    float* Kt = sm + 64 * TP;       // [64][TP]
    float* Vt = sm + 2 * 64 * TP;   // [64][TP]
    float* Ps = sm + 3 * 64 * TP;   // [64][TP]  (r-major: Ps[r*TP + j])

    const int tid = threadIdx.x;
    const int ty  = tid >> 3;       // 0..15
    const int tx  = tid & 7;        // 0..7
    const int qb  = blockIdx.x;     // 0..31
    const int bh  = blockIdx.y;     // 0..31
    const int qr0 = qb * 64;

    const float* Qb = Q + (size_t)bh * SS * DK;
    const float* Kb = K + (size_t)bh * SS * DK;
    const float* Vb = V + (size_t)bh * SS * DK;

    // load Q tile transposed
    for (int qd = tid; qd < 1024; qd += 128) {
        int r  = qd >> 4;
        int c4 = (qd & 15) << 2;
        float4 t = *(const float4*)(Qb + (size_t)(qr0 + r) * DK + c4);
        Qt[(c4 + 0) * TP + r] = t.x; Qt[(c4 + 1) * TP + r] = t.y;
        Qt[(c4 + 2) * TP + r] = t.z; Qt[(c4 + 3) * TP + r] = t.w;
    }

    float o[4][8];
    float m_[4], l_[4];
#pragma unroll
    for (int i = 0; i < 4; i++) {
        m_[i] = -1e30f; l_[i] = 0.f;
#pragma unroll
        for (int j = 0; j < 8; j++) o[i][j] = 0.f;
    }

    const int ntiles = qb + 1;
    for (int t = 0; t < ntiles; ++t) {
        const int kc0 = t * 64;
        __syncthreads();   // protect Kt/Vt/Ps from previous iteration readers
        for (int qd = tid; qd < 1024; qd += 128) {
            int r  = qd >> 4;
            int c4 = (qd & 15) << 2;
            float4 kv = *(const float4*)(Kb + (size_t)(kc0 + r) * DK + c4);
            Kt[(c4 + 0) * TP + r] = kv.x; Kt[(c4 + 1) * TP + r] = kv.y;
            Kt[(c4 + 2) * TP + r] = kv.z; Kt[(c4 + 3) * TP + r] = kv.w;
            float4 vv = *(const float4*)(Vb + (size_t)(kc0 + r) * DK + c4);
            Vt[(c4 + 0) * TP + r] = vv.x; Vt[(c4 + 1) * TP + r] = vv.y;
            Vt[(c4 + 2) * TP + r] = vv.z; Vt[(c4 + 3) * TP + r] = vv.w;
        }
        __syncthreads();

        // S = Q K^T  (4x8 per thread)
        float sc[4][8];
#pragma unroll
        for (int i = 0; i < 4; i++)
#pragma unroll
            for (int j = 0; j < 8; j++) sc[i][j] = 0.f;

#pragma unroll 8
        for (int d = 0; d < 64; ++d) {
            float a[4], b[8];
#pragma unroll
            for (int i = 0; i < 4; i++) a[i] = Qt[d * TP + ty * 4 + i];
#pragma unroll
            for (int j = 0; j < 8; j++) b[j] = Kt[d * TP + tx * 8 + j];
#pragma unroll
            for (int i = 0; i < 4; i++)
#pragma unroll
                for (int j = 0; j < 8; j++)
                    sc[i][j] = fmaf(a[i], b[j], sc[i][j]);
        }

        const bool diag = (t == qb);   // only last tile needs the causal mask
#pragma unroll
        for (int i = 0; i < 4; i++) {
            const int rr = ty * 4 + i;
            float mx = -1e30f;
#pragma unroll
            for (int j = 0; j < 8; j++) {
                float v = sc[i][j] * 0.125f;     // 1/sqrt(64)
                if (diag && (tx * 8 + j > rr)) v = -1e30f;
                sc[i][j] = v;
                mx = fmaxf(mx, v);
            }
            mx = fmaxf(mx, __shfl_xor_sync(0xffffffffu, mx, 1));
            mx = fmaxf(mx, __shfl_xor_sync(0xffffffffu, mx, 2));
            mx = fmaxf(mx, __shfl_xor_sync(0xffffffffu, mx, 4));
            float mnew = fmaxf(m_[i], mx);
            float corr = __expf(m_[i] - mnew);
            m_[i] = mnew;
            float rs = 0.f;
#pragma unroll
            for (int j = 0; j < 8; j++) {
                float p = __expf(sc[i][j] - mnew);
                Ps[rr * TP + tx * 8 + j] = p;
                rs += p;
            }
            rs += __shfl_xor_sync(0xffffffffu, rs, 1);
            rs += __shfl_xor_sync(0xffffffffu, rs, 2);
            rs += __shfl_xor_sync(0xffffffffu, rs, 4);
            l_[i] = l_[i] * corr + rs;
#pragma unroll
            for (int j = 0; j < 8; j++) o[i][j] *= corr;
        }
        __syncthreads();

        // O += P V   (inner over 64 keys)
#pragma unroll 8
        for (int jj = 0; jj < 64; ++jj) {
            float p[4], v[8];
#pragma unroll
            for (int i = 0; i < 4; i++) p[i] = Ps[(ty * 4 + i) * TP + jj];
#pragma unroll
            for (int j = 0; j < 8; j++) v[j] = Vt[(tx * 8 + j) * TP + jj];
#pragma unroll
            for (int i = 0; i < 4; i++)
#pragma unroll
                for (int j = 0; j < 8; j++)
                    o[i][j] = fmaf(p[i], v[j], o[i][j]);
        }
    }

    // epilogue: ctx[b][s][h*64+d]
    const int b = bh >> 4;
    const int h = bh & 15;
#pragma unroll
    for (int i = 0; i < 4; i++) {
        float inv = 1.0f / l_[i];
        int srow = qr0 + ty * 4 + i;
        float* dst = ctx + ((size_t)(b * SS + srow)) * DM + h * 64 + tx * 8;
#pragma unroll
        for (int j = 0; j < 8; j++) dst[j] = o[i][j] * inv;
    }
}

// ---------------------------------------------------------------------------
extern "C" void kernel_launch(void* const* d_in, const int* in_sizes, int n_in,
                              void* d_out, int out_size)
{
    const float* x  = (const float*)d_in[0];
    const float* Wq = (const float*)d_in[1];
    const float* Wk = (const float*)d_in[2];
    const float* Wv = (const float*)d_in[3];
    const float* Wo = (const float*)d_in[4];
    float* out = (float*)d_out;

    float *qp, *kp, *vp, *cp;
    cudaGetSymbolAddress((void**)&qp, g_q);
    cudaGetSymbolAddress((void**)&kp, g_k);
    cudaGetSymbolAddress((void**)&vp, g_v);
    cudaGetSymbolAddress((void**)&cp, g_ctx);

    // 1. QKV projection (fused 3-way)
    sgemm_kernel<0><<<dim3(DM / 128, MTOT / 128, 3), 256>>>(
        x, Wq, Wk, Wv, qp, kp, vp);

    // 2. RoPE on q and k
    {
        int total = 2 * BB * HH * SS * 32;
        rope_kernel<<<(total + 255) / 256, 256>>>(qp, kp);
    }

    // 3. Causal flash attention
    {
        const int smem_bytes = 4 * 64 * TP * sizeof(float);   // 66560
        cudaFuncSetAttribute(flash_kernel,
                             cudaFuncAttributeMaxDynamicSharedMemorySize,
                             smem_bytes);
        flash_kernel<<<dim3(SS / 64, BHT), 128, smem_bytes>>>(qp, kp, vp, cp);
    }

    // 4. Output projection
    sgemm_kernel<1><<<dim3(DM / 128, MTOT / 128, 1), 256>>>(
        cp, Wo, Wo, Wo, out, out, out);
}

// round 4
// speedup vs baseline: 1.5896x; 1.5896x over previous
#include <cuda_runtime.h>
#include <stdint.h>
#include <math.h>

#define BB   2
#define SS   2048
#define HH   16
#define DK   64
#define DM   1024
#define MTOT (BB*SS)          // 4096
#define BHT  (BB*HH)          // 32

// Scratch (allocation-free rule: __device__ globals)
__device__ float g_q[BB*HH*SS*DK];     // [b,h,s,d]
__device__ float g_k[BB*HH*SS*DK];
__device__ float g_v[BB*HH*SS*DK];
__device__ float g_ctx[BB*SS*DM];      // [b,s,dm]

// ---------------------------------------------------------------------------
// TF32 helpers
// ---------------------------------------------------------------------------
__device__ __forceinline__ float to_tf32(float x) {
    uint32_t u;
    asm("cvt.rna.tf32.f32 %0, %1;" : "=r"(u) : "f"(x));
    return __uint_as_float(u);
}

__device__ __forceinline__ void mma_tf32(float c[4],
                                         uint32_t a0, uint32_t a1, uint32_t a2, uint32_t a3,
                                         uint32_t b0, uint32_t b1) {
    asm volatile(
        "mma.sync.aligned.m16n8k8.row.col.f32.tf32.tf32.f32 "
        "{%0,%1,%2,%3}, {%4,%5,%6,%7}, {%8,%9}, {%0,%1,%2,%3};"
        : "+f"(c[0]), "+f"(c[1]), "+f"(c[2]), "+f"(c[3])
        : "r"(a0), "r"(a1), "r"(a2), "r"(a3), "r"(b0), "r"(b1));
}

// ---------------------------------------------------------------------------
// TF32 tensor-core GEMM: C[m][n] = sum_k A[m][k] * W[n][k]
// A: MxK row-major, W: NxK row-major (so B-fragment col-major == W K-contig)
// MODE 0: z in {0,1,2} selects Wq/Wk/Wv, epilogue scatters into [b,h,s,d]
// MODE 1: plain row-major output to C0
// CTA tile 128x128x32, 8 warps (2x4), warp tile 64x32, mma m16n8k8.
// ---------------------------------------------------------------------------
#define LDP 36   // smem row stride: banks (4g + t) mod 32 all distinct

template<int MODE>
__global__ void __launch_bounds__(256, 2)
gemm_tf32_kernel(const float* __restrict__ A,
                 const float* __restrict__ W0, const float* __restrict__ W1,
                 const float* __restrict__ W2,
                 float* __restrict__ C0, float* __restrict__ C1, float* __restrict__ C2)
{
    __shared__ float As[128][LDP];
    __shared__ float Bs[128][LDP];

    const float* W;
    float* C;
    if (MODE == 0) {
        int z = blockIdx.z;
        W = (z == 0) ? W0 : ((z == 1) ? W1 : W2);
        C = (z == 0) ? C0 : ((z == 1) ? C1 : C2);
    } else {
        W = W0; C = C0;
    }

    const int tid   = threadIdx.x;
    const int lane  = tid & 31;
    const int wid   = tid >> 5;
    const int warpM = wid >> 2;     // 0..1  -> 64 rows
    const int warpN = wid & 3;      // 0..3  -> 32 cols
    const int g     = lane >> 2;    // 0..7
    const int t     = lane & 3;     // 0..3

    const int m0 = blockIdx.y * 128;
    const int n0 = blockIdx.x * 128;

    const int ldRow = tid >> 3;         // 0..31
    const int ldCol = (tid & 7) * 4;    // 0,4,...,28

    float acc[4][4][4];
#pragma unroll
    for (int mt = 0; mt < 4; mt++)
#pragma unroll
        for (int nt = 0; nt < 4; nt++)
#pragma unroll
            for (int r = 0; r < 4; r++) acc[mt][nt][r] = 0.f;

    for (int k0 = 0; k0 < DM; k0 += 32) {
#pragma unroll
        for (int p = 0; p < 4; p++) {
            int r = ldRow + p * 32;
            float4 a4 = *(const float4*)(A + (size_t)(m0 + r) * DM + k0 + ldCol);
            As[r][ldCol + 0] = to_tf32(a4.x);
            As[r][ldCol + 1] = to_tf32(a4.y);
            As[r][ldCol + 2] = to_tf32(a4.z);
            As[r][ldCol + 3] = to_tf32(a4.w);
            float4 b4 = *(const float4*)(W + (size_t)(n0 + r) * DM + k0 + ldCol);
            Bs[r][ldCol + 0] = to_tf32(b4.x);
            Bs[r][ldCol + 1] = to_tf32(b4.y);
            Bs[r][ldCol + 2] = to_tf32(b4.z);
            Bs[r][ldCol + 3] = to_tf32(b4.w);
        }
        __syncthreads();

#pragma unroll
        for (int ks = 0; ks < 4; ks++) {
            const int kk = ks * 8;
            uint32_t afr[4][4];
            uint32_t bfr[4][2];
#pragma unroll
            for (int mt = 0; mt < 4; mt++) {
                int row = warpM * 64 + mt * 16 + g;
                afr[mt][0] = __float_as_uint(As[row    ][kk + t    ]);
                afr[mt][1] = __float_as_uint(As[row + 8][kk + t    ]);
                afr[mt][2] = __float_as_uint(As[row    ][kk + t + 4]);
                afr[mt][3] = __float_as_uint(As[row + 8][kk + t + 4]);
            }
#pragma unroll
            for (int nt = 0; nt < 4; nt++) {
                int col = warpN * 32 + nt * 8 + g;
                bfr[nt][0] = __float_as_uint(Bs[col][kk + t    ]);
                bfr[nt][1] = __float_as_uint(Bs[col][kk + t + 4]);
            }
#pragma unroll
            for (int mt = 0; mt < 4; mt++)
#pragma unroll
                for (int nt = 0; nt < 4; nt++)
                    mma_tf32(acc[mt][nt],
                             afr[mt][0], afr[mt][1], afr[mt][2], afr[mt][3],
                             bfr[nt][0], bfr[nt][1]);
        }
        __syncthreads();
    }

    // Epilogue. c0,c1: (row g,   col 2t, 2t+1); c2,c3: (row g+8, col 2t, 2t+1)
#pragma unroll
    for (int mt = 0; mt < 4; mt++) {
#pragma unroll
        for (int nt = 0; nt < 4; nt++) {
            int r0  = m0 + warpM * 64 + mt * 16 + g;
            int col = n0 + warpN * 32 + nt * 8 + 2 * t;
            if (MODE == 0) {
                int h = col >> 6;
                int d = col & 63;
#pragma unroll
                for (int half = 0; half < 2; half++) {
                    int r  = r0 + half * 8;
                    int b_ = r >> 11;
                    int s  = r & 2047;
                    float2* dst = (float2*)(C + ((size_t)((b_ * HH + h) * SS + s)) * DK + d);
                    *dst = make_float2(acc[mt][nt][2 * half], acc[mt][nt][2 * half + 1]);
                }
            } else {
#pragma unroll
                for (int half = 0; half < 2; half++) {
                    int r = r0 + half * 8;
                    float2* dst = (float2*)(C + (size_t)r * DM + col);
                    *dst = make_float2(acc[mt][nt][2 * half], acc[mt][nt][2 * half + 1]);
                }
            }
        }
    }
}

// ---------------------------------------------------------------------------
// RoPE in-place on q and k, layout [b,h,s,d]; pairs (2j, 2j+1), j=0..31
// ---------------------------------------------------------------------------
__global__ void rope_kernel(float* __restrict__ q, float* __restrict__ k)
{
    const int NP = BB * HH * SS * 32;   // pairs per array
    int idx = blockIdx.x * blockDim.x + threadIdx.x;
    if (idx >= 2 * NP) return;
    float* arr = (idx < NP) ? q : k;
    int p = (idx < NP) ? idx : idx - NP;

    int j = p & 31;
    int s = (p >> 5) & 2047;
    size_t base = ((size_t)(p >> 5)) * 64 + 2 * j;

    float inv_freq = exp2f(-(float)j * (13.287712379549449f / 32.0f));
    float ang = (float)s * inv_freq;
    float sn, cs;
    sincosf(ang, &sn, &cs);

    float2* pp = (float2*)(arr + base);
    float2 xv = *pp;
    *pp = make_float2(xv.x * cs - xv.y * sn, xv.x * sn + xv.y * cs);
}

// ---------------------------------------------------------------------------
// Flash attention (causal), fp32. Br=Bc=64, d=64. 128 threads (ty 0..15, tx 0..7)
// ---------------------------------------------------------------------------
#define TP 65   // padded stride

__global__ void __launch_bounds__(128)
flash_kernel(const float* __restrict__ Q, const float* __restrict__ K,
             const float* __restrict__ V, float* __restrict__ ctx)
{
    extern __shared__ float sm[];
    float* Qt = sm;                 // [64][TP]  (d-major: Qt[d*TP + r])
    float* Kt = sm + 64 * TP;       // [64][TP]
    float* Vt = sm + 2 * 64 * TP;   // [64][TP]
    float* Ps = sm + 3 * 64 * TP;   // [64][TP]  (r-major: Ps[r*TP + j])

    const int tid = threadIdx.x;
    const int ty  = tid >> 3;       // 0..15
    const int tx  = tid & 7;        // 0..7
    const int qb  = blockIdx.x;     // 0..31
    const int bh  = blockIdx.y;     // 0..31
    const int qr0 = qb * 64;

    const float* Qb = Q + (size_t)bh * SS * DK;
    const float* Kb = K + (size_t)bh * SS * DK;
    const float* Vb = V + (size_t)bh * SS * DK;

    for (int qd = tid; qd < 1024; qd += 128) {
        int r  = qd >> 4;
        int c4 = (qd & 15) << 2;
        float4 tq = *(const float4*)(Qb + (size_t)(qr0 + r) * DK + c4);
        Qt[(c4 + 0) * TP + r] = tq.x; Qt[(c4 + 1) * TP + r] = tq.y;
        Qt[(c4 + 2) * TP + r] = tq.z; Qt[(c4 + 3) * TP + r] = tq.w;
    }

    float o[4][8];
    float m_[4], l_[4];
#pragma unroll
    for (int i = 0; i < 4; i++) {
        m_[i] = -1e30f; l_[i] = 0.f;
#pragma unroll
        for (int j = 0; j < 8; j++) o[i][j] = 0.f;
    }

    const int ntiles = qb + 1;
    for (int t = 0; t < ntiles; ++t) {
        const int kc0 = t * 64;
        __syncthreads();
        for (int qd = tid; qd < 1024; qd += 128) {
            int r  = qd >> 4;
            int c4 = (qd & 15) << 2;
            float4 kv = *(const float4*)(Kb + (size_t)(kc0 + r) * DK + c4);
            Kt[(c4 + 0) * TP + r] = kv.x; Kt[(c4 + 1) * TP + r] = kv.y;
            Kt[(c4 + 2) * TP + r] = kv.z; Kt[(c4 + 3) * TP + r] = kv.w;
            float4 vv = *(const float4*)(Vb + (size_t)(kc0 + r) * DK + c4);
            Vt[(c4 + 0) * TP + r] = vv.x; Vt[(c4 + 1) * TP + r] = vv.y;
            Vt[(c4 + 2) * TP + r] = vv.z; Vt[(c4 + 3) * TP + r] = vv.w;
        }
        __syncthreads();

        float sc[4][8];
#pragma unroll
        for (int i = 0; i < 4; i++)
#pragma unroll
            for (int j = 0; j < 8; j++) sc[i][j] = 0.f;

#pragma unroll 8
        for (int d = 0; d < 64; ++d) {
            float a[4], b[8];
#pragma unroll
            for (int i = 0; i < 4; i++) a[i] = Qt[d * TP + ty * 4 + i];
#pragma unroll
            for (int j = 0; j < 8; j++) b[j] = Kt[d * TP + tx * 8 + j];
#pragma unroll
            for (int i = 0; i < 4; i++)
#pragma unroll
                for (int j = 0; j < 8; j++)
                    sc[i][j] = fmaf(a[i], b[j], sc[i][j]);
        }

        const bool diag = (t == qb);
#pragma unroll
        for (int i = 0; i < 4; i++) {
            const int rr = ty * 4 + i;
            float mx = -1e30f;
#pragma unroll
            for (int j = 0; j < 8; j++) {
                float v = sc[i][j] * 0.125f;
                if (diag && (tx * 8 + j > rr)) v = -1e30f;
                sc[i][j] = v;
                mx = fmaxf(mx, v);
            }
            mx = fmaxf(mx, __shfl_xor_sync(0xffffffffu, mx, 1));
            mx = fmaxf(mx, __shfl_xor_sync(0xffffffffu, mx, 2));
            mx = fmaxf(mx, __shfl_xor_sync(0xffffffffu, mx, 4));
            float mnew = fmaxf(m_[i], mx);
            float corr = __expf(m_[i] - mnew);
            m_[i] = mnew;
            float rs = 0.f;
#pragma unroll
            for (int j = 0; j < 8; j++) {
                float p = __expf(sc[i][j] - mnew);
                Ps[rr * TP + tx * 8 + j] = p;
                rs += p;
            }
            rs += __shfl_xor_sync(0xffffffffu, rs, 1);
            rs += __shfl_xor_sync(0xffffffffu, rs, 2);
            rs += __shfl_xor_sync(0xffffffffu, rs, 4);
            l_[i] = l_[i] * corr + rs;
#pragma unroll
            for (int j = 0; j < 8; j++) o[i][j] *= corr;
        }
        __syncthreads();

#pragma unroll 8
        for (int jj = 0; jj < 64; ++jj) {
            float p[4], v[8];
#pragma unroll
            for (int i = 0; i < 4; i++) p[i] = Ps[(ty * 4 + i) * TP + jj];
#pragma unroll
            for (int j = 0; j < 8; j++) v[j] = Vt[(tx * 8 + j) * TP + jj];
#pragma unroll
            for (int i = 0; i < 4; i++)
#pragma unroll
                for (int j = 0; j < 8; j++)
                    o[i][j] = fmaf(p[i], v[j], o[i][j]);
        }
    }

    const int b = bh >> 4;
    const int h = bh & 15;
#pragma unroll
    for (int i = 0; i < 4; i++) {
        float inv = 1.0f / l_[i];
        int srow = qr0 + ty * 4 + i;
        float* dst = ctx + ((size_t)(b * SS + srow)) * DM + h * 64 + tx * 8;
#pragma unroll
        for (int j = 0; j < 8; j++) dst[j] = o[i][j] * inv;
    }
}

// ---------------------------------------------------------------------------
extern "C" void kernel_launch(void* const* d_in, const int* in_sizes, int n_in,
                              void* d_out, int out_size)
{
    const float* x  = (const float*)d_in[0];
    const float* Wq = (const float*)d_in[1];
    const float* Wk = (const float*)d_in[2];
    const float* Wv = (const float*)d_in[3];
    const float* Wo = (const float*)d_in[4];
    float* out = (float*)d_out;

    float *qp, *kp, *vp, *cp;
    cudaGetSymbolAddress((void**)&qp, g_q);
    cudaGetSymbolAddress((void**)&kp, g_k);
    cudaGetSymbolAddress((void**)&vp, g_v);
    cudaGetSymbolAddress((void**)&cp, g_ctx);

    // 1. QKV projection (fused 3-way, tf32 tensor cores)
    gemm_tf32_kernel<0><<<dim3(DM / 128, MTOT / 128, 3), 256>>>(
        x, Wq, Wk, Wv, qp, kp, vp);

    // 2. RoPE on q and k
    {
        int total = 2 * BB * HH * SS * 32;
        rope_kernel<<<(total + 255) / 256, 256>>>(qp, kp);
    }

    // 3. Causal flash attention
    {
        const int smem_bytes = 4 * 64 * TP * sizeof(float);   // 66560
        cudaFuncSetAttribute(flash_kernel,
                             cudaFuncAttributeMaxDynamicSharedMemorySize,
                             smem_bytes);
        flash_kernel<<<dim3(SS / 64, BHT), 128, smem_bytes>>>(qp, kp, vp, cp);
    }

    // 4. Output projection (tf32 tensor cores)
    gemm_tf32_kernel<1><<<dim3(DM / 128, MTOT / 128, 1), 256>>>(
        cp, Wo, Wo, Wo, out, out, out);
}

// round 9
// speedup vs baseline: 3.6129x; 2.2728x over previous
#include <cuda_runtime.h>
#include <stdint.h>
#include <math.h>

#define BB   2
#define SS   2048
#define HH   16
#define DK   64
#define DM   1024
#define MTOT (BB*SS)          // 4096
#define BHT  (BB*HH)          // 32

// Scratch (allocation-free rule: __device__ globals)
__device__ float g_q[BB*HH*SS*DK];     // [b,h,s,d]
__device__ float g_k[BB*HH*SS*DK];
__device__ float g_v[BB*HH*SS*DK];
__device__ float g_ctx[BB*SS*DM];      // [b,s,dm]

// ---------------------------------------------------------------------------
// TF32 helpers
// ---------------------------------------------------------------------------
__device__ __forceinline__ float to_tf32(float x) {
    uint32_t u;
    asm("cvt.rna.tf32.f32 %0, %1;" : "=r"(u) : "f"(x));
    return __uint_as_float(u);
}

__device__ __forceinline__ void mma_tf32(float c[4],
                                         uint32_t a0, uint32_t a1, uint32_t a2, uint32_t a3,
                                         uint32_t b0, uint32_t b1) {
    asm volatile(
        "mma.sync.aligned.m16n8k8.row.col.f32.tf32.tf32.f32 "
        "{%0,%1,%2,%3}, {%4,%5,%6,%7}, {%8,%9}, {%0,%1,%2,%3};"
        : "+f"(c[0]), "+f"(c[1]), "+f"(c[2]), "+f"(c[3])
        : "r"(a0), "r"(a1), "r"(a2), "r"(a3), "r"(b0), "r"(b1));
}

__device__ __forceinline__ float ex2(float x) {
    float y;
    asm("ex2.approx.f32 %0, %1;" : "=f"(y) : "f"(x));
    return y;
}

// ---------------------------------------------------------------------------
// TF32 tensor-core GEMM (unchanged from R4): C[m][n] = sum_k A[m][k]*W[n][k]
// ---------------------------------------------------------------------------
#define LDP 36

template<int MODE>
__global__ void __launch_bounds__(256, 2)
gemm_tf32_kernel(const float* __restrict__ A,
                 const float* __restrict__ W0, const float* __restrict__ W1,
                 const float* __restrict__ W2,
                 float* __restrict__ C0, float* __restrict__ C1, float* __restrict__ C2)
{
    __shared__ float As[128][LDP];
    __shared__ float Bs[128][LDP];

    const float* W;
    float* C;
    if (MODE == 0) {
        int z = blockIdx.z;
        W = (z == 0) ? W0 : ((z == 1) ? W1 : W2);
        C = (z == 0) ? C0 : ((z == 1) ? C1 : C2);
    } else {
        W = W0; C = C0;
    }

    const int tid   = threadIdx.x;
    const int lane  = tid & 31;
    const int wid   = tid >> 5;
    const int warpM = wid >> 2;
    const int warpN = wid & 3;
    const int g     = lane >> 2;
    const int t     = lane & 3;

    const int m0 = blockIdx.y * 128;
    const int n0 = blockIdx.x * 128;

    const int ldRow = tid >> 3;
    const int ldCol = (tid & 7) * 4;

    float acc[4][4][4];
#pragma unroll
    for (int mt = 0; mt < 4; mt++)
#pragma unroll
        for (int nt = 0; nt < 4; nt++)
#pragma unroll
            for (int r = 0; r < 4; r++) acc[mt][nt][r] = 0.f;

    for (int k0 = 0; k0 < DM; k0 += 32) {
#pragma unroll
        for (int p = 0; p < 4; p++) {
            int r = ldRow + p * 32;
            float4 a4 = *(const float4*)(A + (size_t)(m0 + r) * DM + k0 + ldCol);
            As[r][ldCol + 0] = to_tf32(a4.x);
            As[r][ldCol + 1] = to_tf32(a4.y);
            As[r][ldCol + 2] = to_tf32(a4.z);
            As[r][ldCol + 3] = to_tf32(a4.w);
            float4 b4 = *(const float4*)(W + (size_t)(n0 + r) * DM + k0 + ldCol);
            Bs[r][ldCol + 0] = to_tf32(b4.x);
            Bs[r][ldCol + 1] = to_tf32(b4.y);
            Bs[r][ldCol + 2] = to_tf32(b4.z);
            Bs[r][ldCol + 3] = to_tf32(b4.w);
        }
        __syncthreads();

#pragma unroll
        for (int ks = 0; ks < 4; ks++) {
            const int kk = ks * 8;
            uint32_t afr[4][4];
            uint32_t bfr[4][2];
#pragma unroll
            for (int mt = 0; mt < 4; mt++) {
                int row = warpM * 64 + mt * 16 + g;
                afr[mt][0] = __float_as_uint(As[row    ][kk + t    ]);
                afr[mt][1] = __float_as_uint(As[row + 8][kk + t    ]);
                afr[mt][2] = __float_as_uint(As[row    ][kk + t + 4]);
                afr[mt][3] = __float_as_uint(As[row + 8][kk + t + 4]);
            }
#pragma unroll
            for (int nt = 0; nt < 4; nt++) {
                int col = warpN * 32 + nt * 8 + g;
                bfr[nt][0] = __float_as_uint(Bs[col][kk + t    ]);
                bfr[nt][1] = __float_as_uint(Bs[col][kk + t + 4]);
            }
#pragma unroll
            for (int mt = 0; mt < 4; mt++)
#pragma unroll
                for (int nt = 0; nt < 4; nt++)
                    mma_tf32(acc[mt][nt],
                             afr[mt][0], afr[mt][1], afr[mt][2], afr[mt][3],
                             bfr[nt][0], bfr[nt][1]);
        }
        __syncthreads();
    }

#pragma unroll
    for (int mt = 0; mt < 4; mt++) {
#pragma unroll
        for (int nt = 0; nt < 4; nt++) {
            int r0  = m0 + warpM * 64 + mt * 16 + g;
            int col = n0 + warpN * 32 + nt * 8 + 2 * t;
            if (MODE == 0) {
                int h = col >> 6;
                int d = col & 63;
#pragma unroll
                for (int half = 0; half < 2; half++) {
                    int r  = r0 + half * 8;
                    int b_ = r >> 11;
                    int s  = r & 2047;
                    float2* dst = (float2*)(C + ((size_t)((b_ * HH + h) * SS + s)) * DK + d);
                    *dst = make_float2(acc[mt][nt][2 * half], acc[mt][nt][2 * half + 1]);
                }
            } else {
#pragma unroll
                for (int half = 0; half < 2; half++) {
                    int r = r0 + half * 8;
                    float2* dst = (float2*)(C + (size_t)r * DM + col);
                    *dst = make_float2(acc[mt][nt][2 * half], acc[mt][nt][2 * half + 1]);
                }
            }
        }
    }
}

// ---------------------------------------------------------------------------
// RoPE in-place on q and k (unchanged)
// ---------------------------------------------------------------------------
__global__ void rope_kernel(float* __restrict__ q, float* __restrict__ k)
{
    const int NP = BB * HH * SS * 32;
    int idx = blockIdx.x * blockDim.x + threadIdx.x;
    if (idx >= 2 * NP) return;
    float* arr = (idx < NP) ? q : k;
    int p = (idx < NP) ? idx : idx - NP;

    int j = p & 31;
    int s = (p >> 5) & 2047;
    size_t base = ((size_t)(p >> 5)) * 64 + 2 * j;

    float inv_freq = exp2f(-(float)j * (13.287712379549449f / 32.0f));
    float ang = (float)s * inv_freq;
    float sn, cs;
    sincosf(ang, &sn, &cs);

    float2* pp = (float2*)(arr + base);
    float2 xv = *pp;
    *pp = make_float2(xv.x * cs - xv.y * sn, xv.x * sn + xv.y * cs);
}

// ---------------------------------------------------------------------------
// Tensor-core flash attention (causal, tf32). Br=128, Bc=64, 256 threads.
// Warp w owns q-rows [w*16, w*16+16). All math in base-2 domain:
// Q pre-scaled by 0.125*log2(e); probabilities via ex2.
// Smem pads: 68 for [row][col] frag reads (banks 4g+t distinct),
//            72 for V (banks t*8+g distinct).
// ---------------------------------------------------------------------------
#define FP 68
#define VP 72
#define SCALE2 0.1803368801111244f   // (1/8) * log2(e)

__global__ void __launch_bounds__(256, 2)
flash_tc_kernel(const float* __restrict__ Q, const float* __restrict__ K,
                const float* __restrict__ V, float* __restrict__ ctx)
{
    extern __shared__ float sm[];
    float* Qs = sm;                         // [128][FP]
    float* Ps = Qs + 128 * FP;              // [128][FP]
    float* Ks = Ps + 128 * FP;              // [64][FP]
    float* Vs = Ks + 64 * FP;               // [64][VP]

    const int tid  = threadIdx.x;
    const int lane = tid & 31;
    const int w    = tid >> 5;              // 0..7
    const int g    = lane >> 2;             // 0..7
    const int t    = lane & 3;              // 0..3

    const int qb  = gridDim.x - 1 - blockIdx.x;   // reversed: heavy CTAs first
    const int bh  = blockIdx.y;
    const int qr0 = qb * 128;

    const float* Qb = Q + (size_t)bh * SS * DK;
    const float* Kb = K + (size_t)bh * SS * DK;
    const float* Vb = V + (size_t)bh * SS * DK;

    // Load Q tile (pre-scaled, tf32) : 128 rows x 64 cols
#pragma unroll
    for (int u = 0; u < 8; u++) {
        int idx = tid + u * 256;            // 0..2047
        int r   = idx >> 4;
        int c4  = (idx & 15) << 2;
        float4 q4 = *(const float4*)(Qb + (size_t)(qr0 + r) * DK + c4);
        float4 s4 = make_float4(to_tf32(q4.x * SCALE2), to_tf32(q4.y * SCALE2),
                                to_tf32(q4.z * SCALE2), to_tf32(q4.w * SCALE2));
        *(float4*)&Qs[r * FP + c4] = s4;
    }

    float of[8][4];                          // O accumulator frags (d tiles)
#pragma unroll
    for (int nt = 0; nt < 8; nt++)
#pragma unroll
        for (int r = 0; r < 4; r++) of[nt][r] = 0.f;
    float m0 = -1e30f, m1 = -1e30f, l0 = 0.f, l1 = 0.f;

    const int row0 = w * 16 + g;             // in-tile row for c0/c1
    const int ntiles = 2 * qb + 2;

    for (int tt = 0; tt < ntiles; ++tt) {
        const int kc0 = tt * 64;
        __syncthreads();                     // prev iter done with Ks/Vs
        // fill K/V tiles (64 x 64 each), tf32
#pragma unroll
        for (int u = 0; u < 4; u++) {
            int idx = tid + u * 256;         // 0..1023
            int r   = idx >> 4;
            int c4  = (idx & 15) << 2;
            float4 k4 = *(const float4*)(Kb + (size_t)(kc0 + r) * DK + c4);
            *(float4*)&Ks[r * FP + c4] = make_float4(to_tf32(k4.x), to_tf32(k4.y),
                                                     to_tf32(k4.z), to_tf32(k4.w));
            float4 v4 = *(const float4*)(Vb + (size_t)(kc0 + r) * DK + c4);
            *(float4*)&Vs[r * VP + c4] = make_float4(to_tf32(v4.x), to_tf32(v4.y),
                                                     to_tf32(v4.z), to_tf32(v4.w));
        }
        __syncthreads();

        // ---- S = Q' K^T (base-2 logits) ----
        float sc[8][4];
#pragma unroll
        for (int nt = 0; nt < 8; nt++)
#pragma unroll
            for (int r = 0; r < 4; r++) sc[nt][r] = 0.f;

#pragma unroll
        for (int kk = 0; kk < 8; kk++) {
            const int kb = kk * 8;
            uint32_t a0 = __float_as_uint(Qs[(w * 16 + g    ) * FP + kb + t    ]);
            uint32_t a1 = __float_as_uint(Qs[(w * 16 + g + 8) * FP + kb + t    ]);
            uint32_t a2 = __float_as_uint(Qs[(w * 16 + g    ) * FP + kb + t + 4]);
            uint32_t a3 = __float_as_uint(Qs[(w * 16 + g + 8) * FP + kb + t + 4]);
#pragma unroll
            for (int nt = 0; nt < 8; nt++) {
                uint32_t b0 = __float_as_uint(Ks[(nt * 8 + g) * FP + kb + t    ]);
                uint32_t b1 = __float_as_uint(Ks[(nt * 8 + g) * FP + kb + t + 4]);
                mma_tf32(sc[nt], a0, a1, a2, a3, b0, b1);
            }
        }

        // ---- causal mask (only last two tiles can cross the diagonal) ----
        if (tt >= 2 * qb) {
            const int rg0 = qr0 + row0;
            const int rg1 = rg0 + 8;
#pragma unroll
            for (int nt = 0; nt < 8; nt++) {
                int jg = kc0 + nt * 8 + 2 * t;
                if (jg     > rg0) sc[nt][0] = -1e30f;
                if (jg + 1 > rg0) sc[nt][1] = -1e30f;
                if (jg     > rg1) sc[nt][2] = -1e30f;
                if (jg + 1 > rg1) sc[nt][3] = -1e30f;
            }
        }

        // ---- online softmax on fragments ----
        float mx0 = -1e30f, mx1 = -1e30f;
#pragma unroll
        for (int nt = 0; nt < 8; nt++) {
            mx0 = fmaxf(mx0, fmaxf(sc[nt][0], sc[nt][1]));
            mx1 = fmaxf(mx1, fmaxf(sc[nt][2], sc[nt][3]));
        }
        mx0 = fmaxf(mx0, __shfl_xor_sync(0xffffffffu, mx0, 1));
        mx0 = fmaxf(mx0, __shfl_xor_sync(0xffffffffu, mx0, 2));
        mx1 = fmaxf(mx1, __shfl_xor_sync(0xffffffffu, mx1, 1));
        mx1 = fmaxf(mx1, __shfl_xor_sync(0xffffffffu, mx1, 2));

        float m0n = fmaxf(m0, mx0);
        float m1n = fmaxf(m1, mx1);
        float corr0 = ex2(m0 - m0n);
        float corr1 = ex2(m1 - m1n);
        m0 = m0n; m1 = m1n;

        float s0 = 0.f, s1 = 0.f;
#pragma unroll
        for (int nt = 0; nt < 8; nt++) {
            float p0 = ex2(sc[nt][0] - m0n);
            float p1 = ex2(sc[nt][1] - m0n);
            float p2 = ex2(sc[nt][2] - m1n);
            float p3 = ex2(sc[nt][3] - m1n);
            s0 += p0 + p1;
            s1 += p2 + p3;
            int cb = nt * 8 + 2 * t;
            *(float2*)&Ps[(w * 16 + g    ) * FP + cb] = make_float2(to_tf32(p0), to_tf32(p1));
            *(float2*)&Ps[(w * 16 + g + 8) * FP + cb] = make_float2(to_tf32(p2), to_tf32(p3));
        }
        s0 += __shfl_xor_sync(0xffffffffu, s0, 1);
        s0 += __shfl_xor_sync(0xffffffffu, s0, 2);
        s1 += __shfl_xor_sync(0xffffffffu, s1, 1);
        s1 += __shfl_xor_sync(0xffffffffu, s1, 2);
        l0 = l0 * corr0 + s0;
        l1 = l1 * corr1 + s1;

#pragma unroll
        for (int nt = 0; nt < 8; nt++) {
            of[nt][0] *= corr0; of[nt][1] *= corr0;
            of[nt][2] *= corr1; of[nt][3] *= corr1;
        }
        __syncwarp();   // Ps rows for this warp are warp-local

        // ---- O += P V ----
#pragma unroll
        for (int kk = 0; kk < 8; kk++) {
            const int kb = kk * 8;
            uint32_t a0 = __float_as_uint(Ps[(w * 16 + g    ) * FP + kb + t    ]);
            uint32_t a1 = __float_as_uint(Ps[(w * 16 + g + 8) * FP + kb + t    ]);
            uint32_t a2 = __float_as_uint(Ps[(w * 16 + g    ) * FP + kb + t + 4]);
            uint32_t a3 = __float_as_uint(Ps[(w * 16 + g + 8) * FP + kb + t + 4]);
#pragma unroll
            for (int nt = 0; nt < 8; nt++) {
                uint32_t b0 = __float_as_uint(Vs[(kb + t    ) * VP + nt * 8 + g]);
                uint32_t b1 = __float_as_uint(Vs[(kb + t + 4) * VP + nt * 8 + g]);
                mma_tf32(of[nt], a0, a1, a2, a3, b0, b1);
            }
        }
    }

    // ---- epilogue: ctx[b][s][h*64+d] ----
    const int b = bh >> 4;
    const int h = bh & 15;
    float inv0 = 1.0f / l0;
    float inv1 = 1.0f / l1;
    int srow0 = qr0 + row0;
    float* dst0 = ctx + ((size_t)(b * SS + srow0)) * DM + h * 64;
    float* dst1 = ctx + ((size_t)(b * SS + srow0 + 8)) * DM + h * 64;
#pragma unroll
    for (int nt = 0; nt < 8; nt++) {
        int cb = nt * 8 + 2 * t;
        *(float2*)&dst0[cb] = make_float2(of[nt][0] * inv0, of[nt][1] * inv0);
        *(float2*)&dst1[cb] = make_float2(of[nt][2] * inv1, of[nt][3] * inv1);
    }
}

// ---------------------------------------------------------------------------
extern "C" void kernel_launch(void* const* d_in, const int* in_sizes, int n_in,
                              void* d_out, int out_size)
{
    const float* x  = (const float*)d_in[0];
    const float* Wq = (const float*)d_in[1];
    const float* Wk = (const float*)d_in[2];
    const float* Wv = (const float*)d_in[3];
    const float* Wo = (const float*)d_in[4];
    float* out = (float*)d_out;

    float *qp, *kp, *vp, *cp;
    cudaGetSymbolAddress((void**)&qp, g_q);
    cudaGetSymbolAddress((void**)&kp, g_k);
    cudaGetSymbolAddress((void**)&vp, g_v);
    cudaGetSymbolAddress((void**)&cp, g_ctx);

    // 1. QKV projection (fused 3-way, tf32 tensor cores)
    gemm_tf32_kernel<0><<<dim3(DM / 128, MTOT / 128, 3), 256>>>(
        x, Wq, Wk, Wv, qp, kp, vp);

    // 2. RoPE on q and k
    {
        int total = 2 * BB * HH * SS * 32;
        rope_kernel<<<(total + 255) / 256, 256>>>(qp, kp);
    }

    // 3. Causal flash attention (tf32 tensor cores)
    {
        const int smem_bytes = (128 * FP + 128 * FP + 64 * FP + 64 * VP) * 4; // 105472
        cudaFuncSetAttribute(flash_tc_kernel,
                             cudaFuncAttributeMaxDynamicSharedMemorySize,
                             smem_bytes);
        flash_tc_kernel<<<dim3(SS / 128, BHT), 256, smem_bytes>>>(qp, kp, vp, cp);
    }

    // 4. Output projection (tf32 tensor cores)
    gemm_tf32_kernel<1><<<dim3(DM / 128, MTOT / 128, 1), 256>>>(
        cp, Wo, Wo, Wo, out, out, out);
}

// round 10
// speedup vs baseline: 3.8187x; 1.0570x over previous
#include <cuda_runtime.h>
#include <stdint.h>
#include <math.h>

#define BB   2
#define SS   2048
#define HH   16
#define DK   64
#define DM   1024
#define MTOT (BB*SS)          // 4096
#define BHT  (BB*HH)          // 32

// Scratch (allocation-free rule: __device__ globals)
__device__ float g_q[BB*HH*SS*DK];     // [b,h,s,d]
__device__ float g_k[BB*HH*SS*DK];
__device__ float g_v[BB*HH*SS*DK];
__device__ float g_ctx[BB*SS*DM];      // [b,s,dm]

// ---------------------------------------------------------------------------
// TF32 helpers
// ---------------------------------------------------------------------------
__device__ __forceinline__ float to_tf32(float x) {
    uint32_t u;
    asm("cvt.rna.tf32.f32 %0, %1;" : "=r"(u) : "f"(x));
    return __uint_as_float(u);
}

__device__ __forceinline__ void mma_tf32(float c[4],
                                         uint32_t a0, uint32_t a1, uint32_t a2, uint32_t a3,
                                         uint32_t b0, uint32_t b1) {
    asm volatile(
        "mma.sync.aligned.m16n8k8.row.col.f32.tf32.tf32.f32 "
        "{%0,%1,%2,%3}, {%4,%5,%6,%7}, {%8,%9}, {%0,%1,%2,%3};"
        : "+f"(c[0]), "+f"(c[1]), "+f"(c[2]), "+f"(c[3])
        : "r"(a0), "r"(a1), "r"(a2), "r"(a3), "r"(b0), "r"(b1));
}

__device__ __forceinline__ float ex2(float x) {
    float y;
    asm("ex2.approx.f32 %0, %1;" : "=f"(y) : "f"(x));
    return y;
}

// ---------------------------------------------------------------------------
// TF32 tensor-core GEMM, double-buffered + software pipelined.
// C[m][n] = sum_k A[m][k] * W[n][k]
// MODE 0: z selects Wq/Wk/Wv; epilogue scatters into [b,h,s,d]; z<2 applies RoPE
// MODE 1: plain row-major output
// CTA tile 128x128x32, 8 warps (2x4), warp tile 64x32, mma m16n8k8.
// ---------------------------------------------------------------------------
#define LDP 36
#define STG (256 * LDP)          // floats per stage (A block + B block)
#define GEMM_SMEM (2 * STG * 4)  // bytes = 73728

#define LOG2_10K_OVER32 (13.287712379549449f / 32.0f)

template<int MODE>
__global__ void __launch_bounds__(256, 2)
gemm_tf32_kernel(const float* __restrict__ A,
                 const float* __restrict__ W0, const float* __restrict__ W1,
                 const float* __restrict__ W2,
                 float* __restrict__ C0, float* __restrict__ C1, float* __restrict__ C2)
{
    extern __shared__ float smg[];

    const float* W;
    float* C;
    int z = 0;
    if (MODE == 0) {
        z = blockIdx.z;
        W = (z == 0) ? W0 : ((z == 1) ? W1 : W2);
        C = (z == 0) ? C0 : ((z == 1) ? C1 : C2);
    } else {
        W = W0; C = C0;
    }

    const int tid   = threadIdx.x;
    const int lane  = tid & 31;
    const int wid   = tid >> 5;
    const int warpM = wid >> 2;
    const int warpN = wid & 3;
    const int g     = lane >> 2;
    const int t     = lane & 3;

    const int m0 = blockIdx.y * 128;
    const int n0 = blockIdx.x * 128;

    const int ldRow = tid >> 3;         // 0..31
    const int ldCol = (tid & 7) * 4;    // 0,4,...,28

    const float* Abase = A + (size_t)(m0 + ldRow) * DM + ldCol;
    const float* Wbase = W + (size_t)(n0 + ldRow) * DM + ldCol;

    float acc[4][4][4];
#pragma unroll
    for (int mt = 0; mt < 4; mt++)
#pragma unroll
        for (int nt = 0; nt < 4; nt++)
#pragma unroll
            for (int r = 0; r < 4; r++) acc[mt][nt][r] = 0.f;

    // ---- prologue: fill stage 0 with tile 0 ----
#pragma unroll
    for (int p = 0; p < 4; p++) {
        int r = ldRow + p * 32;
        float4 a4 = *(const float4*)(Abase + (size_t)p * 32 * DM);
        float* As = smg;               // stage 0: A at 0, B at 128*LDP
        As[r * LDP + ldCol + 0] = to_tf32(a4.x);
        As[r * LDP + ldCol + 1] = to_tf32(a4.y);
        As[r * LDP + ldCol + 2] = to_tf32(a4.z);
        As[r * LDP + ldCol + 3] = to_tf32(a4.w);
        float4 b4 = *(const float4*)(Wbase + (size_t)p * 32 * DM);
        float* Bs = smg + 128 * LDP;
        Bs[r * LDP + ldCol + 0] = to_tf32(b4.x);
        Bs[r * LDP + ldCol + 1] = to_tf32(b4.y);
        Bs[r * LDP + ldCol + 2] = to_tf32(b4.z);
        Bs[r * LDP + ldCol + 3] = to_tf32(b4.w);
    }

    for (int it = 0; it < 32; ++it) {
        __syncthreads();
        const float* Acur = smg + (it & 1) * STG;
        const float* Bcur = Acur + 128 * LDP;
        float* Anx = smg + ((it + 1) & 1) * STG;
        float* Bnx = Anx + 128 * LDP;
        const bool pf = (it + 1) < 32;
        const int kn = (it + 1) * 32;

        float4 sa[2], sb[2];
        if (pf) {
#pragma unroll
            for (int p = 0; p < 2; p++) {
                sa[p] = *(const float4*)(Abase + (size_t)p * 32 * DM + kn);
                sb[p] = *(const float4*)(Wbase + (size_t)p * 32 * DM + kn);
            }
        }

        // ---- compute ks = 0,1 ----
#pragma unroll
        for (int ks = 0; ks < 2; ks++) {
            const int kk = ks * 8;
            uint32_t afr[4][4], bfr[4][2];
#pragma unroll
            for (int mt = 0; mt < 4; mt++) {
                int row = warpM * 64 + mt * 16 + g;
                afr[mt][0] = __float_as_uint(Acur[(row    ) * LDP + kk + t    ]);
                afr[mt][1] = __float_as_uint(Acur[(row + 8) * LDP + kk + t    ]);
                afr[mt][2] = __float_as_uint(Acur[(row    ) * LDP + kk + t + 4]);
                afr[mt][3] = __float_as_uint(Acur[(row + 8) * LDP + kk + t + 4]);
            }
#pragma unroll
            for (int nt = 0; nt < 4; nt++) {
                int col = warpN * 32 + nt * 8 + g;
                bfr[nt][0] = __float_as_uint(Bcur[col * LDP + kk + t    ]);
                bfr[nt][1] = __float_as_uint(Bcur[col * LDP + kk + t + 4]);
            }
#pragma unroll
            for (int mt = 0; mt < 4; mt++)
#pragma unroll
                for (int nt = 0; nt < 4; nt++)
                    mma_tf32(acc[mt][nt],
                             afr[mt][0], afr[mt][1], afr[mt][2], afr[mt][3],
                             bfr[nt][0], bfr[nt][1]);
        }

        if (pf) {
#pragma unroll
            for (int p = 0; p < 2; p++) {
                int r = ldRow + p * 32;
                Anx[r * LDP + ldCol + 0] = to_tf32(sa[p].x);
                Anx[r * LDP + ldCol + 1] = to_tf32(sa[p].y);
                Anx[r * LDP + ldCol + 2] = to_tf32(sa[p].z);
                Anx[r * LDP + ldCol + 3] = to_tf32(sa[p].w);
                Bnx[r * LDP + ldCol + 0] = to_tf32(sb[p].x);
                Bnx[r * LDP + ldCol + 1] = to_tf32(sb[p].y);
                Bnx[r * LDP + ldCol + 2] = to_tf32(sb[p].z);
                Bnx[r * LDP + ldCol + 3] = to_tf32(sb[p].w);
            }
#pragma unroll
            for (int p = 0; p < 2; p++) {
                sa[p] = *(const float4*)(Abase + (size_t)(p + 2) * 32 * DM + kn);
                sb[p] = *(const float4*)(Wbase + (size_t)(p + 2) * 32 * DM + kn);
            }
        }

        // ---- compute ks = 2,3 ----
#pragma unroll
        for (int ks = 2; ks < 4; ks++) {
            const int kk = ks * 8;
            uint32_t afr[4][4], bfr[4][2];
#pragma unroll
            for (int mt = 0; mt < 4; mt++) {
                int row = warpM * 64 + mt * 16 + g;
                afr[mt][0] = __float_as_uint(Acur[(row    ) * LDP + kk + t    ]);
                afr[mt][1] = __float_as_uint(Acur[(row + 8) * LDP + kk + t    ]);
                afr[mt][2] = __float_as_uint(Acur[(row    ) * LDP + kk + t + 4]);
                afr[mt][3] = __float_as_uint(Acur[(row + 8) * LDP + kk + t + 4]);
            }
#pragma unroll
            for (int nt = 0; nt < 4; nt++) {
                int col = warpN * 32 + nt * 8 + g;
                bfr[nt][0] = __float_as_uint(Bcur[col * LDP + kk + t    ]);
                bfr[nt][1] = __float_as_uint(Bcur[col * LDP + kk + t + 4]);
            }
#pragma unroll
            for (int mt = 0; mt < 4; mt++)
#pragma unroll
                for (int nt = 0; nt < 4; nt++)
                    mma_tf32(acc[mt][nt],
                             afr[mt][0], afr[mt][1], afr[mt][2], afr[mt][3],
                             bfr[nt][0], bfr[nt][1]);
        }

        if (pf) {
#pragma unroll
            for (int p = 0; p < 2; p++) {
                int r = ldRow + (p + 2) * 32;
                Anx[r * LDP + ldCol + 0] = to_tf32(sa[p].x);
                Anx[r * LDP + ldCol + 1] = to_tf32(sa[p].y);
                Anx[r * LDP + ldCol + 2] = to_tf32(sa[p].z);
                Anx[r * LDP + ldCol + 3] = to_tf32(sa[p].w);
                Bnx[r * LDP + ldCol + 0] = to_tf32(sb[p].x);
                Bnx[r * LDP + ldCol + 1] = to_tf32(sb[p].y);
                Bnx[r * LDP + ldCol + 2] = to_tf32(sb[p].z);
                Bnx[r * LDP + ldCol + 3] = to_tf32(sb[p].w);
            }
        }
    }

    // ---- epilogue (fused RoPE for MODE 0, z<2) ----
#pragma unroll
    for (int mt = 0; mt < 4; mt++) {
#pragma unroll
        for (int nt = 0; nt < 4; nt++) {
            int r0  = m0 + warpM * 64 + mt * 16 + g;
            int col = n0 + warpN * 32 + nt * 8 + 2 * t;
            if (MODE == 0) {
                int h = col >> 6;
                int d = col & 63;
                float c0_ = acc[mt][nt][0], c1_ = acc[mt][nt][1];
                float c2_ = acc[mt][nt][2], c3_ = acc[mt][nt][3];
                if (z < 2) {
                    // RoPE: pair (even d, odd d) = (c0,c1)/(c2,c3); j = d/2
                    float invf = exp2f(-(float)(d >> 1) * LOG2_10K_OVER32);
#pragma unroll
                    for (int half = 0; half < 2; half++) {
                        int r = r0 + half * 8;
                        int s = r & 2047;
                        float sn, cs;
                        sincosf((float)s * invf, &sn, &cs);
                        float x1 = (half == 0) ? c0_ : c2_;
                        float x2 = (half == 0) ? c1_ : c3_;
                        float e = x1 * cs - x2 * sn;
                        float o = x1 * sn + x2 * cs;
                        if (half == 0) { c0_ = e; c1_ = o; }
                        else           { c2_ = e; c3_ = o; }
                    }
                }
#pragma unroll
                for (int half = 0; half < 2; half++) {
                    int r  = r0 + half * 8;
                    int b_ = r >> 11;
                    int s  = r & 2047;
                    float2* dst = (float2*)(C + ((size_t)((b_ * HH + h) * SS + s)) * DK + d);
                    *dst = (half == 0) ? make_float2(c0_, c1_) : make_float2(c2_, c3_);
                }
            } else {
#pragma unroll
                for (int half = 0; half < 2; half++) {
                    int r = r0 + half * 8;
                    float2* dst = (float2*)(C + (size_t)r * DM + col);
                    *dst = make_float2(acc[mt][nt][2 * half], acc[mt][nt][2 * half + 1]);
                }
            }
        }
    }
}

// ---------------------------------------------------------------------------
// Tensor-core flash attention (causal, tf32). Br=128, Bc=64, 256 threads.
// ---------------------------------------------------------------------------
#define FP 68
#define VP 72
#define SCALE2 0.1803368801111244f   // (1/8) * log2(e)

__global__ void __launch_bounds__(256, 2)
flash_tc_kernel(const float* __restrict__ Q, const float* __restrict__ K,
                const float* __restrict__ V, float* __restrict__ ctx)
{
    extern __shared__ float sm[];
    float* Qs = sm;                         // [128][FP]
    float* Ps = Qs + 128 * FP;              // [128][FP]
    float* Ks = Ps + 128 * FP;              // [64][FP]
    float* Vs = Ks + 64 * FP;               // [64][VP]

    const int tid  = threadIdx.x;
    const int lane = tid & 31;
    const int w    = tid >> 5;
    const int g    = lane >> 2;
    const int t    = lane & 3;

    const int qb  = gridDim.x - 1 - blockIdx.x;
    const int bh  = blockIdx.y;
    const int qr0 = qb * 128;

    const float* Qb = Q + (size_t)bh * SS * DK;
    const float* Kb = K + (size_t)bh * SS * DK;
    const float* Vb = V + (size_t)bh * SS * DK;

#pragma unroll
    for (int u = 0; u < 8; u++) {
        int idx = tid + u * 256;
        int r   = idx >> 4;
        int c4  = (idx & 15) << 2;
        float4 q4 = *(const float4*)(Qb + (size_t)(qr0 + r) * DK + c4);
        float4 s4 = make_float4(to_tf32(q4.x * SCALE2), to_tf32(q4.y * SCALE2),
                                to_tf32(q4.z * SCALE2), to_tf32(q4.w * SCALE2));
        *(float4*)&Qs[r * FP + c4] = s4;
    }

    float of[8][4];
#pragma unroll
    for (int nt = 0; nt < 8; nt++)
#pragma unroll
        for (int r = 0; r < 4; r++) of[nt][r] = 0.f;
    float m0 = -1e30f, m1 = -1e30f, l0 = 0.f, l1 = 0.f;

    const int row0 = w * 16 + g;
    const int ntiles = 2 * qb + 2;

    for (int tt = 0; tt < ntiles; ++tt) {
        const int kc0 = tt * 64;
        __syncthreads();
#pragma unroll
        for (int u = 0; u < 4; u++) {
            int idx = tid + u * 256;
            int r   = idx >> 4;
            int c4  = (idx & 15) << 2;
            float4 k4 = *(const float4*)(Kb + (size_t)(kc0 + r) * DK + c4);
            *(float4*)&Ks[r * FP + c4] = make_float4(to_tf32(k4.x), to_tf32(k4.y),
                                                     to_tf32(k4.z), to_tf32(k4.w));
            float4 v4 = *(const float4*)(Vb + (size_t)(kc0 + r) * DK + c4);
            *(float4*)&Vs[r * VP + c4] = make_float4(to_tf32(v4.x), to_tf32(v4.y),
                                                     to_tf32(v4.z), to_tf32(v4.w));
        }
        __syncthreads();

        float sc[8][4];
#pragma unroll
        for (int nt = 0; nt < 8; nt++)
#pragma unroll
            for (int r = 0; r < 4; r++) sc[nt][r] = 0.f;

#pragma unroll
        for (int kk = 0; kk < 8; kk++) {
            const int kb = kk * 8;
            uint32_t a0 = __float_as_uint(Qs[(w * 16 + g    ) * FP + kb + t    ]);
            uint32_t a1 = __float_as_uint(Qs[(w * 16 + g + 8) * FP + kb + t    ]);
            uint32_t a2 = __float_as_uint(Qs[(w * 16 + g    ) * FP + kb + t + 4]);
            uint32_t a3 = __float_as_uint(Qs[(w * 16 + g + 8) * FP + kb + t + 4]);
#pragma unroll
            for (int nt = 0; nt < 8; nt++) {
                uint32_t b0 = __float_as_uint(Ks[(nt * 8 + g) * FP + kb + t    ]);
                uint32_t b1 = __float_as_uint(Ks[(nt * 8 + g) * FP + kb + t + 4]);
                mma_tf32(sc[nt], a0, a1, a2, a3, b0, b1);
            }
        }

        if (tt >= 2 * qb) {
            const int rg0 = qr0 + row0;
            const int rg1 = rg0 + 8;
#pragma unroll
            for (int nt = 0; nt < 8; nt++) {
                int jg = kc0 + nt * 8 + 2 * t;
                if (jg     > rg0) sc[nt][0] = -1e30f;
                if (jg + 1 > rg0) sc[nt][1] = -1e30f;
                if (jg     > rg1) sc[nt][2] = -1e30f;
                if (jg + 1 > rg1) sc[nt][3] = -1e30f;
            }
        }

        float mx0 = -1e30f, mx1 = -1e30f;
#pragma unroll
        for (int nt = 0; nt < 8; nt++) {
            mx0 = fmaxf(mx0, fmaxf(sc[nt][0], sc[nt][1]));
            mx1 = fmaxf(mx1, fmaxf(sc[nt][2], sc[nt][3]));
        }
        mx0 = fmaxf(mx0, __shfl_xor_sync(0xffffffffu, mx0, 1));
        mx0 = fmaxf(mx0, __shfl_xor_sync(0xffffffffu, mx0, 2));
        mx1 = fmaxf(mx1, __shfl_xor_sync(0xffffffffu, mx1, 1));
        mx1 = fmaxf(mx1, __shfl_xor_sync(0xffffffffu, mx1, 2));

        float m0n = fmaxf(m0, mx0);
        float m1n = fmaxf(m1, mx1);
        float corr0 = ex2(m0 - m0n);
        float corr1 = ex2(m1 - m1n);
        m0 = m0n; m1 = m1n;

        float s0 = 0.f, s1 = 0.f;
#pragma unroll
        for (int nt = 0; nt < 8; nt++) {
            float p0 = ex2(sc[nt][0] - m0n);
            float p1 = ex2(sc[nt][1] - m0n);
            float p2 = ex2(sc[nt][2] - m1n);
            float p3 = ex2(sc[nt][3] - m1n);
            s0 += p0 + p1;
            s1 += p2 + p3;
            int cb = nt * 8 + 2 * t;
            *(float2*)&Ps[(w * 16 + g    ) * FP + cb] = make_float2(to_tf32(p0), to_tf32(p1));
            *(float2*)&Ps[(w * 16 + g + 8) * FP + cb] = make_float2(to_tf32(p2), to_tf32(p3));
        }
        s0 += __shfl_xor_sync(0xffffffffu, s0, 1);
        s0 += __shfl_xor_sync(0xffffffffu, s0, 2);
        s1 += __shfl_xor_sync(0xffffffffu, s1, 1);
        s1 += __shfl_xor_sync(0xffffffffu, s1, 2);
        l0 = l0 * corr0 + s0;
        l1 = l1 * corr1 + s1;

#pragma unroll
        for (int nt = 0; nt < 8; nt++) {
            of[nt][0] *= corr0; of[nt][1] *= corr0;
            of[nt][2] *= corr1; of[nt][3] *= corr1;
        }
        __syncwarp();

#pragma unroll
        for (int kk = 0; kk < 8; kk++) {
            const int kb = kk * 8;
            uint32_t a0 = __float_as_uint(Ps[(w * 16 + g    ) * FP + kb + t    ]);
            uint32_t a1 = __float_as_uint(Ps[(w * 16 + g + 8) * FP + kb + t    ]);
            uint32_t a2 = __float_as_uint(Ps[(w * 16 + g    ) * FP + kb + t + 4]);
            uint32_t a3 = __float_as_uint(Ps[(w * 16 + g + 8) * FP + kb + t + 4]);
#pragma unroll
            for (int nt = 0; nt < 8; nt++) {
                uint32_t b0 = __float_as_uint(Vs[(kb + t    ) * VP + nt * 8 + g]);
                uint32_t b1 = __float_as_uint(Vs[(kb + t + 4) * VP + nt * 8 + g]);
                mma_tf32(of[nt], a0, a1, a2, a3, b0, b1);
            }
        }
    }

    const int b = bh >> 4;
    const int h = bh & 15;
    float inv0 = 1.0f / l0;
    float inv1 = 1.0f / l1;
    int srow0 = qr0 + row0;
    float* dst0 = ctx + ((size_t)(b * SS + srow0)) * DM + h * 64;
    float* dst1 = ctx + ((size_t)(b * SS + srow0 + 8)) * DM + h * 64;
#pragma unroll
    for (int nt = 0; nt < 8; nt++) {
        int cb = nt * 8 + 2 * t;
        *(float2*)&dst0[cb] = make_float2(of[nt][0] * inv0, of[nt][1] * inv0);
        *(float2*)&dst1[cb] = make_float2(of[nt][2] * inv1, of[nt][3] * inv1);
    }
}

// ---------------------------------------------------------------------------
extern "C" void kernel_launch(void* const* d_in, const int* in_sizes, int n_in,
                              void* d_out, int out_size)
{
    const float* x  = (const float*)d_in[0];
    const float* Wq = (const float*)d_in[1];
    const float* Wk = (const float*)d_in[2];
    const float* Wv = (const float*)d_in[3];
    const float* Wo = (const float*)d_in[4];
    float* out = (float*)d_out;

    float *qp, *kp, *vp, *cp;
    cudaGetSymbolAddress((void**)&qp, g_q);
    cudaGetSymbolAddress((void**)&kp, g_k);
    cudaGetSymbolAddress((void**)&vp, g_v);
    cudaGetSymbolAddress((void**)&cp, g_ctx);

    cudaFuncSetAttribute(gemm_tf32_kernel<0>,
                         cudaFuncAttributeMaxDynamicSharedMemorySize, GEMM_SMEM);
    cudaFuncSetAttribute(gemm_tf32_kernel<1>,
                         cudaFuncAttributeMaxDynamicSharedMemorySize, GEMM_SMEM);

    // 1. QKV projection (fused 3-way, tf32 TC, pipelined, RoPE fused for Q/K)
    gemm_tf32_kernel<0><<<dim3(DM / 128, MTOT / 128, 3), 256, GEMM_SMEM>>>(
        x, Wq, Wk, Wv, qp, kp, vp);

    // 2. Causal flash attention (tf32 tensor cores)
    {
        const int smem_bytes = (128 * FP + 128 * FP + 64 * FP + 64 * VP) * 4; // 105472
        cudaFuncSetAttribute(flash_tc_kernel,
                             cudaFuncAttributeMaxDynamicSharedMemorySize,
                             smem_bytes);
        flash_tc_kernel<<<dim3(SS / 128, BHT), 256, smem_bytes>>>(qp, kp, vp, cp);
    }

    // 3. Output projection (tf32 tensor cores, pipelined)
    gemm_tf32_kernel<1><<<dim3(DM / 128, MTOT / 128, 1), 256, GEMM_SMEM>>>(
        cp, Wo, Wo, Wo, out, out, out);
}